// round 5
// baseline (speedup 1.0000x reference)
#include <cuda_runtime.h>

static constexpr int CHW     = 3 * 128 * 128;    // 49152 floats
static constexpr int CHW4    = CHW / 4;          // 12288 float4
static constexpr int S       = 16;
static constexpr int N       = 64;
static constexpr int SGROUPS = 4;                // 4 samples per block
static constexpr int CHUNKS  = 4;                // CHW4 split 4 ways
static constexpr int CHUNK4  = CHW4 / CHUNKS;    // 3072 float4
static constexpr int SUBS    = 4;                // sub-chunks per chunk (warps/sample)
static constexpr int SUB4    = CHUNK4 / SUBS;    // 768 float4 -> 24 iters/lane
static constexpr int GRID    = N * SGROUPS * CHUNKS;   // 1024 blocks

// one partial per (n, s, chunk, sub) = 64*16*4*4 = 16384
__device__ float        g_partial[N * S * CHUNKS * SUBS];
__device__ unsigned int g_count = 0;

__device__ __forceinline__ float4 ldcg4(const float4* p) {
    float4 v;
    asm volatile("ld.global.cg.v4.f32 {%0,%1,%2,%3}, [%4];"
                 : "=f"(v.x), "=f"(v.y), "=f"(v.z), "=f"(v.w) : "l"(p));
    return v;
}
__device__ __forceinline__ float ldcg1(const float* p) {
    float v;
    asm volatile("ld.global.cg.f32 %0, [%1];" : "=f"(v) : "l"(p));
    return v;
}

__global__ __launch_bounds__(512)
void fused_min_dist_kernel(const float* __restrict__ inputs,
                           const float* __restrict__ samples,
                           float* __restrict__ out) {
    const int blk = blockIdx.x;                   // 0..1023
    const int n   = blk >> 4;                     // /16
    const int sg  = (blk >> 2) & 3;               // sample group 0..3
    const int c   = blk & 3;                      // chunk 0..3

    const int w    = threadIdx.x >> 5;            // warp 0..15
    const int l    = threadIdx.x & 31;
    const int sloc = w & 3;                       // sample within group
    const int sub  = w >> 2;                      // sub-chunk 0..3
    const int s    = sg * 4 + sloc;               // sample 0..15

    const size_t off = (size_t)c * CHUNK4 + (size_t)sub * SUB4;
    const float4* __restrict__ in4 =
        reinterpret_cast<const float4*>(inputs + (size_t)n * CHW) + off;
    const float4* __restrict__ sm4 =
        reinterpret_cast<const float4*>(samples + ((size_t)n * S + s) * CHW) + off;

    // Warps {4k..4k+3} share the same input sub-chunk (L1 reuse x4);
    // samples stream through L2 only (.cg) so they don't evict input lines.
    float acc = 0.0f;
    #pragma unroll 8
    for (int i = l; i < SUB4; i += 32) {
        float4 a = in4[i];          // L1-cached, shared across 4 warps
        float4 b = ldcg4(&sm4[i]);  // L2-only streaming
        float dx = b.x - a.x;
        float dy = b.y - a.y;
        float dz = b.z - a.z;
        float dw = b.w - a.w;
        acc = fmaf(dx, dx, acc);
        acc = fmaf(dy, dy, acc);
        acc = fmaf(dz, dz, acc);
        acc = fmaf(dw, dw, acc);
    }

    #pragma unroll
    for (int o = 16; o > 0; o >>= 1)
        acc += __shfl_down_sync(0xffffffffu, acc, o);
    if (l == 0)
        g_partial[(((size_t)n * S + s) * CHUNKS + c) * SUBS + sub] = acc;

    // ---- last-block-finishes final reduction ----
    __shared__ bool is_last;
    __threadfence();
    __syncthreads();
    if (threadIdx.x == 0) {
        unsigned int prev = atomicInc(&g_count, GRID - 1);   // self-resetting
        is_last = (prev == GRID - 1);
    }
    __syncthreads();

    if (is_last) {
        __shared__ float sh[N * S];
        // 1024 (n,s) pairs / 512 threads = 2 each; 16 partials per pair.
        #pragma unroll
        for (int r = 0; r < 2; r++) {
            const int p = threadIdx.x + r * 512;
            float sum = 0.0f;
            #pragma unroll
            for (int k = 0; k < CHUNKS * SUBS; k++)
                sum += ldcg1(&g_partial[(size_t)p * CHUNKS * SUBS + k]);
            sh[p] = sum;
        }
        __syncthreads();

        __shared__ float mins[N];
        if (threadIdx.x < N) {
            const int nn = threadIdx.x;
            float m = sh[nn * S];
            #pragma unroll
            for (int ss = 1; ss < S; ss++)
                m = fminf(m, sh[nn * S + ss]);
            mins[nn] = m;
        }
        __syncthreads();

        if (threadIdx.x == 0) {
            float total = 0.0f;
            #pragma unroll
            for (int nn = 0; nn < N; nn++)
                total += mins[nn];          // fixed order -> deterministic
            out[0] = total;
        }
    }
}

extern "C" void kernel_launch(void* const* d_in, const int* in_sizes, int n_in,
                              void* d_out, int out_size) {
    const float* inputs  = (const float*)d_in[0];   // [64,3,128,128]
    const float* samples = (const float*)d_in[1];   // [64,16,3,128,128]
    float* out = (float*)d_out;

    fused_min_dist_kernel<<<GRID, 512>>>(inputs, samples, out);
}

// round 8
// speedup vs baseline: 1.1447x; 1.1447x over previous
#include <cuda_runtime.h>

static constexpr int CHW     = 3 * 128 * 128;    // 49152 floats
static constexpr int CHW4    = CHW / 4;          // 12288 float4
static constexpr int S       = 16;
static constexpr int N       = 64;
static constexpr int SG      = 4;                // sample groups (4 samples each)
static constexpr int CHUNKS  = 4;
static constexpr int CHUNK4  = CHW4 / CHUNKS;    // 3072 float4 per chunk
static constexpr int GRID    = N * SG * CHUNKS;  // 1024 blocks

// one partial per (n, s, chunk): 64*16*4 = 4096
__device__ float        g_partial[N * S * CHUNKS];
__device__ unsigned int g_count = 0;

__global__ __launch_bounds__(512)
void fused_min_dist_kernel(const float* __restrict__ inputs,
                           const float* __restrict__ samples,
                           float* __restrict__ out) {
    const int blk = blockIdx.x;              // 0..1023
    const int n   = blk >> 4;
    const int sg  = (blk >> 2) & 3;          // sample group: samples 4*sg..4*sg+3
    const int c   = blk & 3;                 // chunk

    const size_t off = (size_t)c * CHUNK4;
    const float4* __restrict__ in4 =
        reinterpret_cast<const float4*>(inputs + (size_t)n * CHW) + off;
    const float4* __restrict__ s0 =
        reinterpret_cast<const float4*>(samples + ((size_t)n * S + 4 * sg + 0) * CHW) + off;
    const float4* __restrict__ s1 =
        reinterpret_cast<const float4*>(samples + ((size_t)n * S + 4 * sg + 1) * CHW) + off;
    const float4* __restrict__ s2 =
        reinterpret_cast<const float4*>(samples + ((size_t)n * S + 4 * sg + 2) * CHW) + off;
    const float4* __restrict__ s3 =
        reinterpret_cast<const float4*>(samples + ((size_t)n * S + 4 * sg + 3) * CHW) + off;

    // Input float4 loaded ONCE into registers, reused for 4 samples.
    // 5 independent plain loads per iter -> compiler front-batches them (high MLP).
    float a0 = 0.0f, a1 = 0.0f, a2 = 0.0f, a3 = 0.0f;
    #pragma unroll 2
    for (int i = threadIdx.x; i < CHUNK4; i += 512) {   // 6 iters/thread
        float4 a  = in4[i];
        float4 b0 = s0[i];
        float4 b1 = s1[i];
        float4 b2 = s2[i];
        float4 b3 = s3[i];

        float dx, dy, dz, dw;
        dx = b0.x - a.x; dy = b0.y - a.y; dz = b0.z - a.z; dw = b0.w - a.w;
        a0 = fmaf(dx, dx, a0); a0 = fmaf(dy, dy, a0);
        a0 = fmaf(dz, dz, a0); a0 = fmaf(dw, dw, a0);
        dx = b1.x - a.x; dy = b1.y - a.y; dz = b1.z - a.z; dw = b1.w - a.w;
        a1 = fmaf(dx, dx, a1); a1 = fmaf(dy, dy, a1);
        a1 = fmaf(dz, dz, a1); a1 = fmaf(dw, dw, a1);
        dx = b2.x - a.x; dy = b2.y - a.y; dz = b2.z - a.z; dw = b2.w - a.w;
        a2 = fmaf(dx, dx, a2); a2 = fmaf(dy, dy, a2);
        a2 = fmaf(dz, dz, a2); a2 = fmaf(dw, dw, a2);
        dx = b3.x - a.x; dy = b3.y - a.y; dz = b3.z - a.z; dw = b3.w - a.w;
        a3 = fmaf(dx, dx, a3); a3 = fmaf(dy, dy, a3);
        a3 = fmaf(dz, dz, a3); a3 = fmaf(dw, dw, a3);
    }

    // Warp-level sums for all 4 accumulators.
    #pragma unroll
    for (int o = 16; o > 0; o >>= 1) {
        a0 += __shfl_down_sync(0xffffffffu, a0, o);
        a1 += __shfl_down_sync(0xffffffffu, a1, o);
        a2 += __shfl_down_sync(0xffffffffu, a2, o);
        a3 += __shfl_down_sync(0xffffffffu, a3, o);
    }
    __shared__ float swarp[16][4];
    const int l = threadIdx.x & 31;
    const int w = threadIdx.x >> 5;
    if (l == 0) {
        swarp[w][0] = a0; swarp[w][1] = a1;
        swarp[w][2] = a2; swarp[w][3] = a3;
    }
    __syncthreads();
    // 4 threads each sum their sample's 16 warp partials (serial, deterministic).
    if (threadIdx.x < 4) {
        const int j = threadIdx.x;
        float v = 0.0f;
        #pragma unroll
        for (int ww = 0; ww < 16; ww++)
            v += swarp[ww][j];
        g_partial[((size_t)n * S + 4 * sg + j) * CHUNKS + c] = v;
    }

    // ---- last-block-finishes final reduction ----
    __shared__ bool is_last;
    __threadfence();
    __syncthreads();
    if (threadIdx.x == 0) {
        unsigned int prev = atomicInc(&g_count, GRID - 1);   // self-resetting
        is_last = (prev == GRID - 1);
    }
    __syncthreads();

    if (is_last) {
        __shared__ float sh[N * S];
        // 1024 (n,s) pairs / 512 threads = 2 each; 4 chunk partials per pair.
        #pragma unroll
        for (int r = 0; r < 2; r++) {
            const int p = threadIdx.x + r * 512;
            float sum = 0.0f;
            #pragma unroll
            for (int k = 0; k < CHUNKS; k++)
                sum += __ldcg(&g_partial[(size_t)p * CHUNKS + k]);  // L1-bypass, coherent
            sh[p] = sum;
        }
        __syncthreads();

        __shared__ float mins[N];
        if (threadIdx.x < N) {
            const int nn = threadIdx.x;
            float m = sh[nn * S];
            #pragma unroll
            for (int ss = 1; ss < S; ss++)
                m = fminf(m, sh[nn * S + ss]);
            mins[nn] = m;
        }
        __syncthreads();

        if (threadIdx.x == 0) {
            float total = 0.0f;
            #pragma unroll
            for (int nn = 0; nn < N; nn++)
                total += mins[nn];          // fixed order -> deterministic
            out[0] = total;
        }
    }
}

extern "C" void kernel_launch(void* const* d_in, const int* in_sizes, int n_in,
                              void* d_out, int out_size) {
    const float* inputs  = (const float*)d_in[0];   // [64,3,128,128]
    const float* samples = (const float*)d_in[1];   // [64,16,3,128,128]
    float* out = (float*)d_out;

    fused_min_dist_kernel<<<GRID, 512>>>(inputs, samples, out);
}